// round 13
// baseline (speedup 1.0000x reference)
#include <cuda_runtime.h>
#include <cuda_fp16.h>
#include <cstdint>

#define T_TOKENS 32768
#define D_DIM    512
#define F_DIM    2048
#define N_EXP    64

#define BM 128
#define BN 128
#define BK 32
#define NTH 256

// smem geometry (bank-conflict-engineered strides)
#define A_ROW_B   80                      // 32 halves + pad -> banks 20r%32, LDSM conflict-free
#define B_ROW_B   272                     // 128 halves + pad -> banks 4k%32, LDSM.T conflict-free
#define A_STAGE_B (BM * A_ROW_B)          // 10240
#define B_STAGE_B (BK * B_ROW_B)          // 8704
#define STAGES    3
#define DSMEM_B   (STAGES * (A_STAGE_B + B_STAGE_B))   // 56832 -> 2 CTAs/SM

#define WELEMS    (N_EXP * D_DIM * F_DIM)              // 67,108,864

// ---------------- device scratch ----------------
__device__ int    g_offsets[N_EXP + 1];
__device__ int    g_tok[T_TOKENS];
__device__ __half g_Xg [(size_t)T_TOKENS * D_DIM];       // 32 MB  fp16 X, expert-gathered order
__device__ __half g_Hh [(size_t)T_TOKENS * F_DIM];       // 128 MB fp16 intermediate (compact)
__device__ __half g_W1h[(size_t)WELEMS];                 // 134 MB
__device__ __half g_W2h[(size_t)WELEMS];                 // 134 MB

// ---------------- helpers ----------------
__device__ __forceinline__ float gelu_exact(float x) {
    return 0.5f * x * (1.0f + erff(x * 0.70710678118654752f));
}

__device__ __forceinline__ uint32_t smem_u32(const void* p) {
    uint32_t a;
    asm("{ .reg .u64 t; cvta.to.shared.u64 t, %1; cvt.u32.u64 %0, t; }" : "=r"(a) : "l"(p));
    return a;
}

__device__ __forceinline__ void cp16(uint32_t dst, const void* src) {
    asm volatile("cp.async.cg.shared.global [%0], [%1], 16;" :: "r"(dst), "l"(src));
}
#define CP_COMMIT() asm volatile("cp.async.commit_group;")

#define LDSM_X4(r, addr) \
    asm volatile("ldmatrix.sync.aligned.m8n8.x4.shared.b16 {%0,%1,%2,%3}, [%4];" \
        : "=r"((r)[0]), "=r"((r)[1]), "=r"((r)[2]), "=r"((r)[3]) : "r"(addr))

#define LDSM_X4_T(r0, r1, r2, r3, addr) \
    asm volatile("ldmatrix.sync.aligned.m8n8.x4.trans.shared.b16 {%0,%1,%2,%3}, [%4];" \
        : "=r"(r0), "=r"(r1), "=r"(r2), "=r"(r3) : "r"(addr))

__device__ __forceinline__ void mma_f16(float* c, const uint32_t* a, const uint32_t* b) {
    asm volatile(
        "mma.sync.aligned.m16n8k16.row.col.f32.f16.f16.f32 "
        "{%0,%1,%2,%3}, {%4,%5,%6,%7}, {%8,%9}, {%0,%1,%2,%3};"
        : "+f"(c[0]), "+f"(c[1]), "+f"(c[2]), "+f"(c[3])
        : "r"(a[0]), "r"(a[1]), "r"(a[2]), "r"(a[3]), "r"(b[0]), "r"(b[1]));
}

__device__ __forceinline__ uint32_t pack_h2(float lo, float hi) {
    uint32_t d;
    asm("cvt.rn.f16x2.f32 %0, %1, %2;" : "=r"(d) : "f"(hi), "f"(lo));  // first src -> upper
    return d;
}

// ---------------- fused dispatch (one CTA) ----------------
__global__ void dispatch_kernel(const int* __restrict__ disp) {
    __shared__ int cnt[N_EXP];
    __shared__ int off[N_EXP];
    const int tid = threadIdx.x;                 // 1024 threads
    if (tid < N_EXP) cnt[tid] = 0;
    __syncthreads();
    for (int t = tid; t < T_TOKENS; t += 1024) atomicAdd(&cnt[disp[t]], 1);
    __syncthreads();
    if (tid == 0) {
        int s = 0;
        for (int e = 0; e < N_EXP; e++) { off[e] = s; g_offsets[e] = s; s += cnt[e]; }
        g_offsets[N_EXP] = s;
    }
    __syncthreads();
    if (tid < N_EXP) cnt[tid] = 0;               // reuse as cursors
    __syncthreads();
    for (int t = tid; t < T_TOKENS; t += 1024) {
        int e = disp[t];
        int p = atomicAdd(&cnt[e], 1);
        g_tok[off[e] + p] = t;
    }
}

// ---------------- gather + convert X: g_Xg[slot] = fp16(X[g_tok[slot]]) ----------------
__global__ void gather_x_kernel(const float* __restrict__ X) {
    const int slot  = blockIdx.x * 2 + (threadIdx.x >> 7);
    const int local = threadIdx.x & 127;
    const int tok   = g_tok[slot];
    float4 v = *reinterpret_cast<const float4*>(&X[(size_t)tok * D_DIM + local * 4]);
    uint2 o;
    o.x = pack_h2(v.x, v.y); o.y = pack_h2(v.z, v.w);
    *reinterpret_cast<uint2*>(&g_Xg[(size_t)slot * D_DIM + local * 4]) = o;
}

// ---------------- W fp32 -> fp16 (standalone, used for W1) ----------------
__global__ void convert_w_kernel(const float* __restrict__ W, __half* __restrict__ Wh) {
    size_t i = ((size_t)blockIdx.x * 256 + threadIdx.x) * 8;
    float4 v0 = *reinterpret_cast<const float4*>(&W[i]);
    float4 v1 = *reinterpret_cast<const float4*>(&W[i + 4]);
    uint4 o;
    o.x = pack_h2(v0.x, v0.y); o.y = pack_h2(v0.z, v0.w);
    o.z = pack_h2(v1.x, v1.y); o.w = pack_h2(v1.z, v1.w);
    *reinterpret_cast<uint4*>(&Wh[i]) = o;
}

// ================= GEMM kernels (fp16 HMMA, dual-operand 3-stage cp.async) =================
// 256 threads = 8 warps in 2(M)x4(N); warp tile 64x32; one __syncthreads per K-tile.

// ---- GEMM1: H = gelu(Xg @ W1h + b1) -> g_Hh (compact). Grid (16, 9, 64). ----
// blockIdx.y == 8: heterogeneous converter CTAs for W2 fp32->fp16 (overlap with GEMM waves).
__global__ __launch_bounds__(NTH, 2) void gemm1_kernel(
    const float* __restrict__ W2, const float* __restrict__ B1)
{
    extern __shared__ char dsm[];
    __shared__ float sbias[BN];

    // ---- converter role ----
    if (blockIdx.y == 8) {
        const int cid = blockIdx.x + 16 * blockIdx.z;          // 0..1023
        const size_t base_i = (size_t)cid * (WELEMS / 1024);   // 65536 elems
        const int tid = threadIdx.x;
#pragma unroll 4
        for (int it = 0; it < 32; it++) {
            size_t i = base_i + (size_t)it * (NTH * 8) + tid * 8;
            float4 v0 = *reinterpret_cast<const float4*>(&W2[i]);
            float4 v1 = *reinterpret_cast<const float4*>(&W2[i + 4]);
            uint4 o;
            o.x = pack_h2(v0.x, v0.y); o.y = pack_h2(v0.z, v0.w);
            o.z = pack_h2(v1.x, v1.y); o.w = pack_h2(v1.z, v1.w);
            *reinterpret_cast<uint4*>(&g_W2h[i]) = o;
        }
        return;
    }

    // ---- GEMM role ----
    const int e    = blockIdx.z;
    const int base = g_offsets[e];
    const int ne   = g_offsets[e + 1] - base;
    const int tm   = blockIdx.y * BM;
    if (tm >= ne) return;
    const int n0   = blockIdx.x * BN;

    const int tid  = threadIdx.x;
    const int warp = tid >> 5, lane = tid & 31;
    const int wm   = (warp & 1) * 64;
    const int wn   = (warp >> 1) * 32;

    if (tid < BN) sbias[tid] = B1[e * F_DIM + n0 + tid];

    const uint32_t sb = smem_u32(dsm);
    uint32_t uA[STAGES], uB[STAGES];
#pragma unroll
    for (int s = 0; s < STAGES; s++) {
        uA[s] = sb + s * A_STAGE_B;
        uB[s] = sb + STAGES * A_STAGE_B + s * B_STAGE_B;
    }

    float acc[4][4][4];
#pragma unroll
    for (int mf = 0; mf < 4; mf++)
#pragma unroll
        for (int nf = 0; nf < 4; nf++)
#pragma unroll
            for (int c = 0; c < 4; c++) acc[mf][nf][c] = 0.f;

    const int KIT = D_DIM / BK;  // 16

    auto load_stage = [&](int kt) {
        const int k0 = kt * BK;
        const int s  = kt % STAGES;
#pragma unroll
        for (int i = 0; i < 2; i++) {                        // A: 128 rows x 4 segs
            int idx = tid + i * NTH;
            int r = idx >> 2, cc = idx & 3;
            int arow = base + tm + r; if (arow > T_TOKENS - 1) arow = T_TOKENS - 1;
            cp16(uA[s] + r * A_ROW_B + cc * 16, &g_Xg[(size_t)arow * D_DIM + k0 + cc * 8]);
        }
#pragma unroll
        for (int i = 0; i < 2; i++) {                        // B: 32 k-rows x 16 segs
            int idx = tid + i * NTH;
            int kr = idx >> 4, seg = idx & 15;
            cp16(uB[s] + kr * B_ROW_B + seg * 16,
                 &g_W1h[((size_t)e * D_DIM + k0 + kr) * F_DIM + n0 + seg * 8]);
        }
        CP_COMMIT();
    };

    load_stage(0);
    load_stage(1);

    for (int kt = 0; kt < KIT; kt++) {
        if (kt + 1 < KIT) { asm volatile("cp.async.wait_group 1;"); }
        else              { asm volatile("cp.async.wait_group 0;"); }
        __syncthreads();
        if (kt + 2 < KIT) load_stage(kt + 2);
        const uint32_t ua = uA[kt % STAGES];
        const uint32_t ub = uB[kt % STAGES];
#pragma unroll
        for (int c = 0; c < 2; c++) {
            uint32_t a[4][4];
#pragma unroll
            for (int mf = 0; mf < 4; mf++) {
                int row = wm + mf * 16 + (lane & 7) + ((lane >> 3) & 1) * 8;
                LDSM_X4(a[mf], ua + row * A_ROW_B + ((lane >> 4) + 2 * c) * 16);
            }
            uint32_t b[4][2];
#pragma unroll
            for (int p = 0; p < 2; p++) {
                int k = c * 16 + ((lane >> 3) & 1) * 8 + (lane & 7);
                int n = wn + p * 16 + (lane >> 4) * 8;
                uint32_t r0, r1, r2, r3;
                LDSM_X4_T(r0, r1, r2, r3, ub + k * B_ROW_B + n * 2);
                b[2 * p][0] = r0; b[2 * p][1] = r1;
                b[2 * p + 1][0] = r2; b[2 * p + 1][1] = r3;
            }
#pragma unroll
            for (int mf = 0; mf < 4; mf++)
#pragma unroll
                for (int nf = 0; nf < 4; nf++)
                    mma_f16(acc[mf][nf], a[mf], b[nf]);
        }
    }

    // epilogue: bias + exact gelu -> fp16 g_Hh (compact rows)
    const int g = lane >> 2, t2 = lane & 3;
#pragma unroll
    for (int mf = 0; mf < 4; mf++) {
#pragma unroll
        for (int nf = 0; nf < 4; nf++) {
            int row0 = wm + mf * 16 + g;
            int colL = wn + nf * 8 + t2 * 2;
            float b0 = sbias[colL], b1 = sbias[colL + 1];
            int lr = tm + row0;
            if (lr < ne) {
                uint32_t h = pack_h2(gelu_exact(acc[mf][nf][0] + b0),
                                     gelu_exact(acc[mf][nf][1] + b1));
                *reinterpret_cast<uint32_t*>(&g_Hh[(size_t)(base + lr) * F_DIM + n0 + colL]) = h;
            }
            if (lr + 8 < ne) {
                uint32_t h = pack_h2(gelu_exact(acc[mf][nf][2] + b0),
                                     gelu_exact(acc[mf][nf][3] + b1));
                *reinterpret_cast<uint32_t*>(&g_Hh[(size_t)(base + lr + 8) * F_DIM + n0 + colL]) = h;
            }
        }
    }
}

// ---- GEMM2: out = Hh @ W2h + b2, scattered fp32. Grid (4, 8, 64). ----
__global__ __launch_bounds__(NTH, 2) void gemm2_kernel(const float* __restrict__ B2,
                                                       float* __restrict__ out)
{
    extern __shared__ char dsm[];
    __shared__ int   stoks[BM];
    __shared__ float sbias[BN];

    const int e    = blockIdx.z;
    const int base = g_offsets[e];
    const int ne   = g_offsets[e + 1] - base;
    const int tm   = blockIdx.y * BM;
    if (tm >= ne) return;
    const int n0   = blockIdx.x * BN;

    const int tid  = threadIdx.x;
    const int warp = tid >> 5, lane = tid & 31;
    const int wm   = (warp & 1) * 64;
    const int wn   = (warp >> 1) * 32;

    if (tid < BM) stoks[tid] = (tm + tid < ne) ? g_tok[base + tm + tid] : -1;
    if (tid < BN) sbias[tid] = B2[e * D_DIM + n0 + tid];

    const uint32_t sb = smem_u32(dsm);
    uint32_t uA[STAGES], uB[STAGES];
#pragma unroll
    for (int s = 0; s < STAGES; s++) {
        uA[s] = sb + s * A_STAGE_B;
        uB[s] = sb + STAGES * A_STAGE_B + s * B_STAGE_B;
    }

    float acc[4][4][4];
#pragma unroll
    for (int mf = 0; mf < 4; mf++)
#pragma unroll
        for (int nf = 0; nf < 4; nf++)
#pragma unroll
            for (int c = 0; c < 4; c++) acc[mf][nf][c] = 0.f;

    const int KIT = F_DIM / BK;  // 64

    auto load_stage = [&](int kt) {
        const int k0 = kt * BK;
        const int s  = kt % STAGES;
#pragma unroll
        for (int i = 0; i < 2; i++) {
            int idx = tid + i * NTH;
            int r = idx >> 2, cc = idx & 3;
            int arow = base + tm + r; if (arow > T_TOKENS - 1) arow = T_TOKENS - 1;
            cp16(uA[s] + r * A_ROW_B + cc * 16, &g_Hh[(size_t)arow * F_DIM + k0 + cc * 8]);
        }
#pragma unroll
        for (int i = 0; i < 2; i++) {
            int idx = tid + i * NTH;
            int kr = idx >> 4, seg = idx & 15;
            cp16(uB[s] + kr * B_ROW_B + seg * 16,
                 &g_W2h[((size_t)e * F_DIM + k0 + kr) * D_DIM + n0 + seg * 8]);
        }
        CP_COMMIT();
    };

    load_stage(0);
    load_stage(1);

    for (int kt = 0; kt < KIT; kt++) {
        if (kt + 1 < KIT) { asm volatile("cp.async.wait_group 1;"); }
        else              { asm volatile("cp.async.wait_group 0;"); }
        __syncthreads();
        if (kt + 2 < KIT) load_stage(kt + 2);
        const uint32_t ua = uA[kt % STAGES];
        const uint32_t ub = uB[kt % STAGES];
#pragma unroll
        for (int c = 0; c < 2; c++) {
            uint32_t a[4][4];
#pragma unroll
            for (int mf = 0; mf < 4; mf++) {
                int row = wm + mf * 16 + (lane & 7) + ((lane >> 3) & 1) * 8;
                LDSM_X4(a[mf], ua + row * A_ROW_B + ((lane >> 4) + 2 * c) * 16);
            }
            uint32_t b[4][2];
#pragma unroll
            for (int p = 0; p < 2; p++) {
                int k = c * 16 + ((lane >> 3) & 1) * 8 + (lane & 7);
                int n = wn + p * 16 + (lane >> 4) * 8;
                uint32_t r0, r1, r2, r3;
                LDSM_X4_T(r0, r1, r2, r3, ub + k * B_ROW_B + n * 2);
                b[2 * p][0] = r0; b[2 * p][1] = r1;
                b[2 * p + 1][0] = r2; b[2 * p + 1][1] = r3;
            }
#pragma unroll
            for (int mf = 0; mf < 4; mf++)
#pragma unroll
                for (int nf = 0; nf < 4; nf++)
                    mma_f16(acc[mf][nf], a[mf], b[nf]);
        }
    }

    // epilogue: bias + scatter fp32
    const int g = lane >> 2, t2 = lane & 3;
#pragma unroll
    for (int mf = 0; mf < 4; mf++) {
#pragma unroll
        for (int nf = 0; nf < 4; nf++) {
            int row0 = wm + mf * 16 + g;
            int colL = wn + nf * 8 + t2 * 2;
            float b0 = sbias[colL], b1 = sbias[colL + 1];
            int lr = tm + row0;
            if (lr < ne) {
                int tok = stoks[row0];
                float2 o = make_float2(acc[mf][nf][0] + b0, acc[mf][nf][1] + b1);
                *reinterpret_cast<float2*>(&out[(size_t)tok * D_DIM + n0 + colL]) = o;
            }
            if (lr + 8 < ne) {
                int tok = stoks[row0 + 8];
                float2 o = make_float2(acc[mf][nf][2] + b0, acc[mf][nf][3] + b1);
                *reinterpret_cast<float2*>(&out[(size_t)tok * D_DIM + n0 + colL]) = o;
            }
        }
    }
}

// ---------------- launch ----------------
extern "C" void kernel_launch(void* const* d_in, const int* in_sizes, int n_in,
                              void* d_out, int out_size)
{
    const float* X    = (const float*)d_in[0];
    const int*   disp = (const int*)d_in[1];
    const float* W1   = (const float*)d_in[2];
    const float* B1   = (const float*)d_in[3];
    const float* W2   = (const float*)d_in[4];
    const float* B2   = (const float*)d_in[5];
    float*       out  = (float*)d_out;

    cudaFuncSetAttribute(gemm1_kernel, cudaFuncAttributeMaxDynamicSharedMemorySize, DSMEM_B);
    cudaFuncSetAttribute(gemm2_kernel, cudaFuncAttributeMaxDynamicSharedMemorySize, DSMEM_B);

    __half* w1h; cudaGetSymbolAddress((void**)&w1h, g_W1h);

    dispatch_kernel<<<1, 1024>>>(disp);
    gather_x_kernel<<<T_TOKENS / 2, 256>>>(X);
    convert_w_kernel<<<WELEMS / (256 * 8), 256>>>(W1, w1h);
    // gemm1 also converts W2 -> g_W2h via its blockIdx.y==8 converter CTAs
    gemm1_kernel<<<dim3(F_DIM / BN, 9, N_EXP), NTH, DSMEM_B>>>(W2, B1);
    gemm2_kernel<<<dim3(D_DIM / BN, 8, N_EXP), NTH, DSMEM_B>>>(B2, out);
}

// round 14
// speedup vs baseline: 1.4496x; 1.4496x over previous
#include <cuda_runtime.h>
#include <cuda_fp16.h>
#include <cstdint>

#define T_TOKENS 32768
#define D_DIM    512
#define F_DIM    2048
#define N_EXP    64

#define BM 128
#define BN 128
#define BK 32
#define NTH 128

// smem geometry (bank-conflict-engineered strides)
#define A_ROW_B   80                      // 32 halves + pad -> banks 20r%32, LDSM conflict-free
#define B_ROW_B   272                     // 128 halves + pad -> banks 4k%32, LDSM.T conflict-free
#define A_STAGE_B (BM * A_ROW_B)          // 10240
#define B_STAGE_B (BK * B_ROW_B)          // 8704
#define STAGES    3
#define DSMEM_B   (STAGES * (A_STAGE_B + B_STAGE_B))   // 56832 -> 2 CTAs/SM

#define WELEMS    (N_EXP * D_DIM * F_DIM)              // 67,108,864

// ---------------- device scratch ----------------
__device__ int    g_offsets[N_EXP + 1];
__device__ int    g_tok[T_TOKENS];
__device__ __half g_Xg [(size_t)T_TOKENS * D_DIM];       // 32 MB  fp16 X, expert-gathered order
__device__ __half g_Hh [(size_t)T_TOKENS * F_DIM];       // 128 MB fp16 intermediate (compact)
__device__ __half g_W1h[(size_t)WELEMS];                 // 134 MB
__device__ __half g_W2h[(size_t)WELEMS];                 // 134 MB

// ---------------- helpers ----------------
__device__ __forceinline__ float gelu_exact(float x) {
    return 0.5f * x * (1.0f + erff(x * 0.70710678118654752f));
}

__device__ __forceinline__ uint32_t smem_u32(const void* p) {
    uint32_t a;
    asm("{ .reg .u64 t; cvta.to.shared.u64 t, %1; cvt.u32.u64 %0, t; }" : "=r"(a) : "l"(p));
    return a;
}

__device__ __forceinline__ void cp16(uint32_t dst, const void* src) {
    asm volatile("cp.async.cg.shared.global [%0], [%1], 16;" :: "r"(dst), "l"(src));
}
#define CP_COMMIT() asm volatile("cp.async.commit_group;")

#define LDSM_X4(r, addr) \
    asm volatile("ldmatrix.sync.aligned.m8n8.x4.shared.b16 {%0,%1,%2,%3}, [%4];" \
        : "=r"((r)[0]), "=r"((r)[1]), "=r"((r)[2]), "=r"((r)[3]) : "r"(addr))

#define LDSM_X4_T(r0, r1, r2, r3, addr) \
    asm volatile("ldmatrix.sync.aligned.m8n8.x4.trans.shared.b16 {%0,%1,%2,%3}, [%4];" \
        : "=r"(r0), "=r"(r1), "=r"(r2), "=r"(r3) : "r"(addr))

__device__ __forceinline__ void mma_f16(float* c, const uint32_t* a, const uint32_t* b) {
    asm volatile(
        "mma.sync.aligned.m16n8k16.row.col.f32.f16.f16.f32 "
        "{%0,%1,%2,%3}, {%4,%5,%6,%7}, {%8,%9}, {%0,%1,%2,%3};"
        : "+f"(c[0]), "+f"(c[1]), "+f"(c[2]), "+f"(c[3])
        : "r"(a[0]), "r"(a[1]), "r"(a[2]), "r"(a[3]), "r"(b[0]), "r"(b[1]));
}

__device__ __forceinline__ uint32_t pack_h2(float lo, float hi) {
    uint32_t d;
    asm("cvt.rn.f16x2.f32 %0, %1, %2;" : "=r"(d) : "f"(hi), "f"(lo));  // first src -> upper
    return d;
}

// ---------------- fused dispatch (one CTA) ----------------
__global__ void dispatch_kernel(const int* __restrict__ disp) {
    __shared__ int cnt[N_EXP];
    __shared__ int off[N_EXP];
    const int tid = threadIdx.x;                 // 1024 threads
    if (tid < N_EXP) cnt[tid] = 0;
    __syncthreads();
    for (int t = tid; t < T_TOKENS; t += 1024) atomicAdd(&cnt[disp[t]], 1);
    __syncthreads();
    if (tid == 0) {
        int s = 0;
        for (int e = 0; e < N_EXP; e++) { off[e] = s; g_offsets[e] = s; s += cnt[e]; }
        g_offsets[N_EXP] = s;
    }
    __syncthreads();
    if (tid < N_EXP) cnt[tid] = 0;               // reuse as cursors
    __syncthreads();
    for (int t = tid; t < T_TOKENS; t += 1024) {
        int e = disp[t];
        int p = atomicAdd(&cnt[e], 1);
        g_tok[off[e] + p] = t;
    }
}

// ---------------- gather + convert X: g_Xg[slot] = fp16(X[g_tok[slot]]) ----------------
__global__ void gather_x_kernel(const float* __restrict__ X) {
    const int slot  = blockIdx.x * 2 + (threadIdx.x >> 7);
    const int local = threadIdx.x & 127;
    const int tok   = g_tok[slot];
    float4 v = *reinterpret_cast<const float4*>(&X[(size_t)tok * D_DIM + local * 4]);
    uint2 o;
    o.x = pack_h2(v.x, v.y); o.y = pack_h2(v.z, v.w);
    *reinterpret_cast<uint2*>(&g_Xg[(size_t)slot * D_DIM + local * 4]) = o;
}

// ---------------- W fp32 -> fp16 (standalone, used for W1) ----------------
__global__ void convert_w_kernel(const float* __restrict__ W, __half* __restrict__ Wh) {
    size_t i = ((size_t)blockIdx.x * 256 + threadIdx.x) * 8;
    float4 v0 = *reinterpret_cast<const float4*>(&W[i]);
    float4 v1 = *reinterpret_cast<const float4*>(&W[i + 4]);
    uint4 o;
    o.x = pack_h2(v0.x, v0.y); o.y = pack_h2(v0.z, v0.w);
    o.z = pack_h2(v1.x, v1.y); o.w = pack_h2(v1.z, v1.w);
    *reinterpret_cast<uint4*>(&Wh[i]) = o;
}

// ================= GEMM kernels (fp16 HMMA, dual-operand 3-stage cp.async) =================
// 128 threads = 4 warps (2x2), warp tile 64x64; both K-chunks' fragments preloaded
// (16 LDSM pipeline through LSU while chunk-0 MMAs execute). One __syncthreads per K-tile.

// ---- GEMM1: H = gelu(Xg @ W1h + b1) -> g_Hh (compact). Grid (16, 9, 64). ----
// blockIdx.y == 8: heterogeneous converter CTAs for W2 fp32->fp16 (overlap with GEMM waves).
__global__ __launch_bounds__(NTH, 2) void gemm1_kernel(
    const float* __restrict__ W2, const float* __restrict__ B1)
{
    extern __shared__ char dsm[];
    __shared__ float sbias[BN];

    // ---- converter role ----
    if (blockIdx.y == 8) {
        const int cid = blockIdx.x + 16 * blockIdx.z;          // 0..1023
        const size_t base_i = (size_t)cid * (WELEMS / 1024);   // 65536 elems
        const int tid = threadIdx.x;
#pragma unroll 4
        for (int it = 0; it < 64; it++) {
            size_t i = base_i + (size_t)it * 1024 + tid * 8;
            float4 v0 = *reinterpret_cast<const float4*>(&W2[i]);
            float4 v1 = *reinterpret_cast<const float4*>(&W2[i + 4]);
            uint4 o;
            o.x = pack_h2(v0.x, v0.y); o.y = pack_h2(v0.z, v0.w);
            o.z = pack_h2(v1.x, v1.y); o.w = pack_h2(v1.z, v1.w);
            *reinterpret_cast<uint4*>(&g_W2h[i]) = o;
        }
        return;
    }

    // ---- GEMM role ----
    const int e    = blockIdx.z;
    const int base = g_offsets[e];
    const int ne   = g_offsets[e + 1] - base;
    const int tm   = blockIdx.y * BM;
    if (tm >= ne) return;
    const int n0   = blockIdx.x * BN;

    const int tid  = threadIdx.x;
    const int warp = tid >> 5, lane = tid & 31;
    const int wm   = (warp & 1) * 64;
    const int wn   = (warp >> 1) * 64;

    sbias[tid] = B1[e * F_DIM + n0 + tid];

    const uint32_t sb = smem_u32(dsm);
    uint32_t uA[STAGES], uB[STAGES];
#pragma unroll
    for (int s = 0; s < STAGES; s++) {
        uA[s] = sb + s * A_STAGE_B;
        uB[s] = sb + STAGES * A_STAGE_B + s * B_STAGE_B;
    }

    float acc[4][8][4];
#pragma unroll
    for (int mf = 0; mf < 4; mf++)
#pragma unroll
        for (int nf = 0; nf < 8; nf++)
#pragma unroll
            for (int c = 0; c < 4; c++) acc[mf][nf][c] = 0.f;

    const int KIT = D_DIM / BK;  // 16

    auto load_stage = [&](int kt) {
        const int k0 = kt * BK;
        const int s  = kt % STAGES;
#pragma unroll
        for (int i = 0; i < 4; i++) {                        // A: 128 rows x 4 segs
            int idx = tid + i * NTH;
            int r = idx >> 2, cc = idx & 3;
            int arow = base + tm + r; if (arow > T_TOKENS - 1) arow = T_TOKENS - 1;
            cp16(uA[s] + r * A_ROW_B + cc * 16, &g_Xg[(size_t)arow * D_DIM + k0 + cc * 8]);
        }
#pragma unroll
        for (int i = 0; i < 4; i++) {                        // B: 32 k-rows x 16 segs
            int idx = tid + i * NTH;
            int kr = idx >> 4, seg = idx & 15;
            cp16(uB[s] + kr * B_ROW_B + seg * 16,
                 &g_W1h[((size_t)e * D_DIM + k0 + kr) * F_DIM + n0 + seg * 8]);
        }
        CP_COMMIT();
    };

    load_stage(0);
    load_stage(1);

    for (int kt = 0; kt < KIT; kt++) {
        if (kt + 1 < KIT) { asm volatile("cp.async.wait_group 1;"); }
        else              { asm volatile("cp.async.wait_group 0;"); }
        __syncthreads();
        if (kt + 2 < KIT) load_stage(kt + 2);
        const uint32_t ua = uA[kt % STAGES];
        const uint32_t ub = uB[kt % STAGES];

        // preload BOTH K-chunks' fragments; LDSM pipeline overlaps chunk-0 MMAs
        uint32_t a[2][4][4];
        uint32_t b[2][8][2];
#pragma unroll
        for (int c = 0; c < 2; c++) {
#pragma unroll
            for (int mf = 0; mf < 4; mf++) {
                int row = wm + mf * 16 + (lane & 7) + ((lane >> 3) & 1) * 8;
                LDSM_X4(a[c][mf], ua + row * A_ROW_B + ((lane >> 4) + 2 * c) * 16);
            }
#pragma unroll
            for (int p = 0; p < 4; p++) {
                int k = c * 16 + ((lane >> 3) & 1) * 8 + (lane & 7);
                int n = wn + p * 16 + (lane >> 4) * 8;
                uint32_t r0, r1, r2, r3;
                LDSM_X4_T(r0, r1, r2, r3, ub + k * B_ROW_B + n * 2);
                b[c][2 * p][0] = r0; b[c][2 * p][1] = r1;
                b[c][2 * p + 1][0] = r2; b[c][2 * p + 1][1] = r3;
            }
        }
#pragma unroll
        for (int c = 0; c < 2; c++)
#pragma unroll
            for (int mf = 0; mf < 4; mf++)
#pragma unroll
                for (int nf = 0; nf < 8; nf++)
                    mma_f16(acc[mf][nf], a[c][mf], b[c][nf]);
    }

    // epilogue: bias + exact gelu -> fp16 g_Hh (compact rows)
    const int g = lane >> 2, t2 = lane & 3;
#pragma unroll
    for (int mf = 0; mf < 4; mf++) {
#pragma unroll
        for (int nf = 0; nf < 8; nf++) {
            int row0 = wm + mf * 16 + g;
            int colL = wn + nf * 8 + t2 * 2;
            float b0 = sbias[colL], b1 = sbias[colL + 1];
            int lr = tm + row0;
            if (lr < ne) {
                uint32_t h = pack_h2(gelu_exact(acc[mf][nf][0] + b0),
                                     gelu_exact(acc[mf][nf][1] + b1));
                *reinterpret_cast<uint32_t*>(&g_Hh[(size_t)(base + lr) * F_DIM + n0 + colL]) = h;
            }
            if (lr + 8 < ne) {
                uint32_t h = pack_h2(gelu_exact(acc[mf][nf][2] + b0),
                                     gelu_exact(acc[mf][nf][3] + b1));
                *reinterpret_cast<uint32_t*>(&g_Hh[(size_t)(base + lr + 8) * F_DIM + n0 + colL]) = h;
            }
        }
    }
}

// ---- GEMM2: out = Hh @ W2h + b2, scattered fp32. Grid (4, 8, 64). ----
__global__ __launch_bounds__(NTH, 2) void gemm2_kernel(const float* __restrict__ B2,
                                                       float* __restrict__ out)
{
    extern __shared__ char dsm[];
    __shared__ int   stoks[BM];
    __shared__ float sbias[BN];

    const int e    = blockIdx.z;
    const int base = g_offsets[e];
    const int ne   = g_offsets[e + 1] - base;
    const int tm   = blockIdx.y * BM;
    if (tm >= ne) return;
    const int n0   = blockIdx.x * BN;

    const int tid  = threadIdx.x;
    const int warp = tid >> 5, lane = tid & 31;
    const int wm   = (warp & 1) * 64;
    const int wn   = (warp >> 1) * 64;

    stoks[tid] = (tm + tid < ne) ? g_tok[base + tm + tid] : -1;
    sbias[tid] = B2[e * D_DIM + n0 + tid];

    const uint32_t sb = smem_u32(dsm);
    uint32_t uA[STAGES], uB[STAGES];
#pragma unroll
    for (int s = 0; s < STAGES; s++) {
        uA[s] = sb + s * A_STAGE_B;
        uB[s] = sb + STAGES * A_STAGE_B + s * B_STAGE_B;
    }

    float acc[4][8][4];
#pragma unroll
    for (int mf = 0; mf < 4; mf++)
#pragma unroll
        for (int nf = 0; nf < 8; nf++)
#pragma unroll
            for (int c = 0; c < 4; c++) acc[mf][nf][c] = 0.f;

    const int KIT = F_DIM / BK;  // 64

    auto load_stage = [&](int kt) {
        const int k0 = kt * BK;
        const int s  = kt % STAGES;
#pragma unroll
        for (int i = 0; i < 4; i++) {
            int idx = tid + i * NTH;
            int r = idx >> 2, cc = idx & 3;
            int arow = base + tm + r; if (arow > T_TOKENS - 1) arow = T_TOKENS - 1;
            cp16(uA[s] + r * A_ROW_B + cc * 16, &g_Hh[(size_t)arow * F_DIM + k0 + cc * 8]);
        }
#pragma unroll
        for (int i = 0; i < 4; i++) {
            int idx = tid + i * NTH;
            int kr = idx >> 4, seg = idx & 15;
            cp16(uB[s] + kr * B_ROW_B + seg * 16,
                 &g_W2h[((size_t)e * F_DIM + k0 + kr) * D_DIM + n0 + seg * 8]);
        }
        CP_COMMIT();
    };

    load_stage(0);
    load_stage(1);

    for (int kt = 0; kt < KIT; kt++) {
        if (kt + 1 < KIT) { asm volatile("cp.async.wait_group 1;"); }
        else              { asm volatile("cp.async.wait_group 0;"); }
        __syncthreads();
        if (kt + 2 < KIT) load_stage(kt + 2);
        const uint32_t ua = uA[kt % STAGES];
        const uint32_t ub = uB[kt % STAGES];

        uint32_t a[2][4][4];
        uint32_t b[2][8][2];
#pragma unroll
        for (int c = 0; c < 2; c++) {
#pragma unroll
            for (int mf = 0; mf < 4; mf++) {
                int row = wm + mf * 16 + (lane & 7) + ((lane >> 3) & 1) * 8;
                LDSM_X4(a[c][mf], ua + row * A_ROW_B + ((lane >> 4) + 2 * c) * 16);
            }
#pragma unroll
            for (int p = 0; p < 4; p++) {
                int k = c * 16 + ((lane >> 3) & 1) * 8 + (lane & 7);
                int n = wn + p * 16 + (lane >> 4) * 8;
                uint32_t r0, r1, r2, r3;
                LDSM_X4_T(r0, r1, r2, r3, ub + k * B_ROW_B + n * 2);
                b[c][2 * p][0] = r0; b[c][2 * p][1] = r1;
                b[c][2 * p + 1][0] = r2; b[c][2 * p + 1][1] = r3;
            }
        }
#pragma unroll
        for (int c = 0; c < 2; c++)
#pragma unroll
            for (int mf = 0; mf < 4; mf++)
#pragma unroll
                for (int nf = 0; nf < 8; nf++)
                    mma_f16(acc[mf][nf], a[c][mf], b[c][nf]);
    }

    // epilogue: bias + scatter fp32
    const int g = lane >> 2, t2 = lane & 3;
#pragma unroll
    for (int mf = 0; mf < 4; mf++) {
#pragma unroll
        for (int nf = 0; nf < 8; nf++) {
            int row0 = wm + mf * 16 + g;
            int colL = wn + nf * 8 + t2 * 2;
            float b0 = sbias[colL], b1 = sbias[colL + 1];
            int lr = tm + row0;
            if (lr < ne) {
                int tok = stoks[row0];
                float2 o = make_float2(acc[mf][nf][0] + b0, acc[mf][nf][1] + b1);
                *reinterpret_cast<float2*>(&out[(size_t)tok * D_DIM + n0 + colL]) = o;
            }
            if (lr + 8 < ne) {
                int tok = stoks[row0 + 8];
                float2 o = make_float2(acc[mf][nf][2] + b0, acc[mf][nf][3] + b1);
                *reinterpret_cast<float2*>(&out[(size_t)tok * D_DIM + n0 + colL]) = o;
            }
        }
    }
}

// ---------------- launch ----------------
extern "C" void kernel_launch(void* const* d_in, const int* in_sizes, int n_in,
                              void* d_out, int out_size)
{
    const float* X    = (const float*)d_in[0];
    const int*   disp = (const int*)d_in[1];
    const float* W1   = (const float*)d_in[2];
    const float* B1   = (const float*)d_in[3];
    const float* W2   = (const float*)d_in[4];
    const float* B2   = (const float*)d_in[5];
    float*       out  = (float*)d_out;

    cudaFuncSetAttribute(gemm1_kernel, cudaFuncAttributeMaxDynamicSharedMemorySize, DSMEM_B);
    cudaFuncSetAttribute(gemm2_kernel, cudaFuncAttributeMaxDynamicSharedMemorySize, DSMEM_B);

    __half* w1h; cudaGetSymbolAddress((void**)&w1h, g_W1h);

    dispatch_kernel<<<1, 1024>>>(disp);
    gather_x_kernel<<<T_TOKENS / 2, 256>>>(X);
    convert_w_kernel<<<WELEMS / (256 * 8), 256>>>(W1, w1h);
    // gemm1 also converts W2 -> g_W2h via its blockIdx.y==8 converter CTAs
    gemm1_kernel<<<dim3(F_DIM / BN, 9, N_EXP), NTH, DSMEM_B>>>(W2, B1);
    gemm2_kernel<<<dim3(D_DIM / BN, 8, N_EXP), NTH, DSMEM_B>>>(B2, out);
}

// round 15
// speedup vs baseline: 1.5101x; 1.0417x over previous
#include <cuda_runtime.h>
#include <cuda_fp16.h>
#include <cstdint>

#define T_TOKENS 32768
#define D_DIM    512
#define F_DIM    2048
#define N_EXP    64

#define BM 128
#define BN 128
#define BK 64
#define NTH 128

// smem geometry (bank-conflict-engineered strides)
#define A_ROW_B   144                     // 64 halves(128B) + 16B pad -> row starts 4 banks apart
#define B_ROW_B   272                     // 128 halves(256B) + 16B pad -> 4 banks apart
#define A_STAGE_B (BM * A_ROW_B)          // 18432
#define B_STAGE_B (BK * B_ROW_B)          // 17408
#define STAGES    3
#define DSMEM_B   (STAGES * (A_STAGE_B + B_STAGE_B))   // 107520 -> 2 CTAs/SM (215KB/228KB)

#define WELEMS    (N_EXP * D_DIM * F_DIM)              // 67,108,864
#define PAD_ROWS  128

// ---------------- device scratch ----------------
__device__ int    g_offsets[N_EXP + 1];
__device__ int    g_tok[T_TOKENS];
__device__ __half g_Xg [(size_t)(T_TOKENS + PAD_ROWS) * D_DIM];   // fp16 X, expert order (+pad)
__device__ __half g_Hh [(size_t)(T_TOKENS + PAD_ROWS) * F_DIM];   // fp16 intermediate (+pad)
__device__ __half g_W1h[(size_t)WELEMS];                 // 134 MB
__device__ __half g_W2h[(size_t)WELEMS];                 // 134 MB

// ---------------- helpers ----------------
__device__ __forceinline__ float gelu_exact(float x) {
    return 0.5f * x * (1.0f + erff(x * 0.70710678118654752f));
}

__device__ __forceinline__ uint32_t smem_u32(const void* p) {
    uint32_t a;
    asm("{ .reg .u64 t; cvta.to.shared.u64 t, %1; cvt.u32.u64 %0, t; }" : "=r"(a) : "l"(p));
    return a;
}

__device__ __forceinline__ void cp16(uint32_t dst, const void* src) {
    asm volatile("cp.async.cg.shared.global [%0], [%1], 16;" :: "r"(dst), "l"(src));
}
#define CP_COMMIT() asm volatile("cp.async.commit_group;")

#define LDSM_X4(r, addr) \
    asm volatile("ldmatrix.sync.aligned.m8n8.x4.shared.b16 {%0,%1,%2,%3}, [%4];" \
        : "=r"((r)[0]), "=r"((r)[1]), "=r"((r)[2]), "=r"((r)[3]) : "r"(addr))

#define LDSM_X4_T(r0, r1, r2, r3, addr) \
    asm volatile("ldmatrix.sync.aligned.m8n8.x4.trans.shared.b16 {%0,%1,%2,%3}, [%4];" \
        : "=r"(r0), "=r"(r1), "=r"(r2), "=r"(r3) : "r"(addr))

__device__ __forceinline__ void mma_f16(float* c, const uint32_t* a, const uint32_t* b) {
    asm volatile(
        "mma.sync.aligned.m16n8k16.row.col.f32.f16.f16.f32 "
        "{%0,%1,%2,%3}, {%4,%5,%6,%7}, {%8,%9}, {%0,%1,%2,%3};"
        : "+f"(c[0]), "+f"(c[1]), "+f"(c[2]), "+f"(c[3])
        : "r"(a[0]), "r"(a[1]), "r"(a[2]), "r"(a[3]), "r"(b[0]), "r"(b[1]));
}

__device__ __forceinline__ uint32_t pack_h2(float lo, float hi) {
    uint32_t d;
    asm("cvt.rn.f16x2.f32 %0, %1, %2;" : "=r"(d) : "f"(hi), "f"(lo));  // first src -> upper
    return d;
}

// ---------------- fused dispatch (one CTA) ----------------
__global__ void dispatch_kernel(const int* __restrict__ disp) {
    __shared__ int cnt[N_EXP];
    __shared__ int off[N_EXP];
    const int tid = threadIdx.x;                 // 1024 threads
    if (tid < N_EXP) cnt[tid] = 0;
    __syncthreads();
    for (int t = tid; t < T_TOKENS; t += 1024) atomicAdd(&cnt[disp[t]], 1);
    __syncthreads();
    if (tid == 0) {
        int s = 0;
        for (int e = 0; e < N_EXP; e++) { off[e] = s; g_offsets[e] = s; s += cnt[e]; }
        g_offsets[N_EXP] = s;
    }
    __syncthreads();
    if (tid < N_EXP) cnt[tid] = 0;               // reuse as cursors
    __syncthreads();
    for (int t = tid; t < T_TOKENS; t += 1024) {
        int e = disp[t];
        int p = atomicAdd(&cnt[e], 1);
        g_tok[off[e] + p] = t;
    }
}

// ---------------- gather + convert X: g_Xg[slot] = fp16(X[g_tok[slot]]) ----------------
__global__ void gather_x_kernel(const float* __restrict__ X) {
    const int slot  = blockIdx.x * 2 + (threadIdx.x >> 7);
    const int local = threadIdx.x & 127;
    const int tok   = g_tok[slot];
    float4 v = *reinterpret_cast<const float4*>(&X[(size_t)tok * D_DIM + local * 4]);
    uint2 o;
    o.x = pack_h2(v.x, v.y); o.y = pack_h2(v.z, v.w);
    *reinterpret_cast<uint2*>(&g_Xg[(size_t)slot * D_DIM + local * 4]) = o;
}

// ---------------- W fp32 -> fp16 (standalone, used for W1) ----------------
__global__ void convert_w_kernel(const float* __restrict__ W, __half* __restrict__ Wh) {
    size_t i = ((size_t)blockIdx.x * 256 + threadIdx.x) * 8;
    float4 v0 = *reinterpret_cast<const float4*>(&W[i]);
    float4 v1 = *reinterpret_cast<const float4*>(&W[i + 4]);
    uint4 o;
    o.x = pack_h2(v0.x, v0.y); o.y = pack_h2(v0.z, v0.w);
    o.z = pack_h2(v1.x, v1.y); o.w = pack_h2(v1.z, v1.w);
    *reinterpret_cast<uint4*>(&Wh[i]) = o;
}

// ================= GEMM kernels (fp16 HMMA, BK=64, 3-stage cp.async) =================
// 128 threads = 4 warps (2x2), warp tile 64x64; 4 k16-chunks per tile; 1 barrier/tile.

// ---- GEMM1: H = gelu(Xg @ W1h + b1) -> g_Hh (compact). Grid (16, 9, 64). ----
// blockIdx.y == 8: heterogeneous converter CTAs for W2 fp32->fp16 (overlap with GEMM waves).
__global__ __launch_bounds__(NTH, 2) void gemm1_kernel(
    const float* __restrict__ W2, const float* __restrict__ B1)
{
    extern __shared__ char dsm[];
    __shared__ float sbias[BN];

    // ---- converter role ----
    if (blockIdx.y == 8) {
        const int cid = blockIdx.x + 16 * blockIdx.z;          // 0..1023
        const size_t base_i = (size_t)cid * (WELEMS / 1024);   // 65536 elems
        const int tid = threadIdx.x;
#pragma unroll 4
        for (int it = 0; it < 64; it++) {
            size_t i = base_i + (size_t)it * 1024 + tid * 8;
            float4 v0 = *reinterpret_cast<const float4*>(&W2[i]);
            float4 v1 = *reinterpret_cast<const float4*>(&W2[i + 4]);
            uint4 o;
            o.x = pack_h2(v0.x, v0.y); o.y = pack_h2(v0.z, v0.w);
            o.z = pack_h2(v1.x, v1.y); o.w = pack_h2(v1.z, v1.w);
            *reinterpret_cast<uint4*>(&g_W2h[i]) = o;
        }
        return;
    }

    // ---- GEMM role ----
    const int e    = blockIdx.z;
    const int base = g_offsets[e];
    const int ne   = g_offsets[e + 1] - base;
    const int tm   = blockIdx.y * BM;
    if (tm >= ne) return;
    const int n0   = blockIdx.x * BN;

    const int tid  = threadIdx.x;
    const int warp = tid >> 5, lane = tid & 31;
    const int wm   = (warp & 1) * 64;
    const int wn   = (warp >> 1) * 64;

    sbias[tid] = B1[e * F_DIM + n0 + tid];

    const uint32_t sb = smem_u32(dsm);
    uint32_t uA[STAGES], uB[STAGES];
#pragma unroll
    for (int s = 0; s < STAGES; s++) {
        uA[s] = sb + s * A_STAGE_B;
        uB[s] = sb + STAGES * A_STAGE_B + s * B_STAGE_B;
    }

    // per-thread loader bases (strength-reduced; constants folded per i)
    const __half* aptr = g_Xg + ((size_t)(base + tm) + (tid >> 3)) * D_DIM + (tid & 7) * 8;
    const __half* bptr = g_W1h + ((size_t)e * D_DIM + (tid >> 4)) * F_DIM + n0 + (tid & 15) * 8;
    const uint32_t sa_o = (tid >> 3) * A_ROW_B + (tid & 7) * 16;
    const uint32_t sb_o = (tid >> 4) * B_ROW_B + (tid & 15) * 16;

    float acc[4][8][4];
#pragma unroll
    for (int mf = 0; mf < 4; mf++)
#pragma unroll
        for (int nf = 0; nf < 8; nf++)
#pragma unroll
            for (int c = 0; c < 4; c++) acc[mf][nf][c] = 0.f;

    const int KIT = D_DIM / BK;  // 8

    auto load_stage = [&](int kt) {
        const int s = kt % STAGES;
        const __half* ap = aptr + kt * BK;
        const __half* bp = bptr + (size_t)kt * BK * F_DIM;
#pragma unroll
        for (int i = 0; i < 8; i++)    // A: 128 rows x 128B (this thread: rows r0+16i)
            cp16(uA[s] + sa_o + i * (16 * A_ROW_B), ap + (size_t)i * 16 * D_DIM);
#pragma unroll
        for (int i = 0; i < 8; i++)    // B: 64 rows x 256B (rows k0+8i)
            cp16(uB[s] + sb_o + i * (8 * B_ROW_B), bp + (size_t)i * 8 * F_DIM);
        CP_COMMIT();
    };

    load_stage(0);
    load_stage(1);

    for (int kt = 0; kt < KIT; kt++) {
        if (kt + 1 < KIT) { asm volatile("cp.async.wait_group 1;"); }
        else              { asm volatile("cp.async.wait_group 0;"); }
        __syncthreads();
        if (kt + 2 < KIT) load_stage(kt + 2);
        const uint32_t ua = uA[kt % STAGES];
        const uint32_t ub = uB[kt % STAGES];
#pragma unroll
        for (int c = 0; c < 4; c++) {
            uint32_t a[4][4];
#pragma unroll
            for (int mf = 0; mf < 4; mf++) {
                int row = wm + mf * 16 + (lane & 7) + ((lane >> 3) & 1) * 8;
                LDSM_X4(a[mf], ua + row * A_ROW_B + c * 32 + (lane >> 4) * 16);
            }
            uint32_t b[8][2];
#pragma unroll
            for (int p = 0; p < 4; p++) {
                int k = c * 16 + ((lane >> 3) & 1) * 8 + (lane & 7);
                int n = wn + p * 16 + (lane >> 4) * 8;
                uint32_t r0, r1, r2, r3;
                LDSM_X4_T(r0, r1, r2, r3, ub + k * B_ROW_B + n * 2);
                b[2 * p][0] = r0; b[2 * p][1] = r1;
                b[2 * p + 1][0] = r2; b[2 * p + 1][1] = r3;
            }
#pragma unroll
            for (int mf = 0; mf < 4; mf++)
#pragma unroll
                for (int nf = 0; nf < 8; nf++)
                    mma_f16(acc[mf][nf], a[mf], b[nf]);
        }
    }

    // epilogue: bias + exact gelu -> fp16 g_Hh (compact rows)
    const int g = lane >> 2, t2 = lane & 3;
#pragma unroll
    for (int mf = 0; mf < 4; mf++) {
#pragma unroll
        for (int nf = 0; nf < 8; nf++) {
            int row0 = wm + mf * 16 + g;
            int colL = wn + nf * 8 + t2 * 2;
            float b0 = sbias[colL], b1 = sbias[colL + 1];
            int lr = tm + row0;
            if (lr < ne) {
                uint32_t h = pack_h2(gelu_exact(acc[mf][nf][0] + b0),
                                     gelu_exact(acc[mf][nf][1] + b1));
                *reinterpret_cast<uint32_t*>(&g_Hh[(size_t)(base + lr) * F_DIM + n0 + colL]) = h;
            }
            if (lr + 8 < ne) {
                uint32_t h = pack_h2(gelu_exact(acc[mf][nf][2] + b0),
                                     gelu_exact(acc[mf][nf][3] + b1));
                *reinterpret_cast<uint32_t*>(&g_Hh[(size_t)(base + lr + 8) * F_DIM + n0 + colL]) = h;
            }
        }
    }
}

// ---- GEMM2: out = Hh @ W2h + b2, scattered fp32. Grid (4, 8, 64). ----
__global__ __launch_bounds__(NTH, 2) void gemm2_kernel(const float* __restrict__ B2,
                                                       float* __restrict__ out)
{
    extern __shared__ char dsm[];
    __shared__ int   stoks[BM];
    __shared__ float sbias[BN];

    const int e    = blockIdx.z;
    const int base = g_offsets[e];
    const int ne   = g_offsets[e + 1] - base;
    const int tm   = blockIdx.y * BM;
    if (tm >= ne) return;
    const int n0   = blockIdx.x * BN;

    const int tid  = threadIdx.x;
    const int warp = tid >> 5, lane = tid & 31;
    const int wm   = (warp & 1) * 64;
    const int wn   = (warp >> 1) * 64;

    stoks[tid] = (tm + tid < ne) ? g_tok[base + tm + tid] : -1;
    sbias[tid] = B2[e * D_DIM + n0 + tid];

    const uint32_t sb = smem_u32(dsm);
    uint32_t uA[STAGES], uB[STAGES];
#pragma unroll
    for (int s = 0; s < STAGES; s++) {
        uA[s] = sb + s * A_STAGE_B;
        uB[s] = sb + STAGES * A_STAGE_B + s * B_STAGE_B;
    }

    const __half* aptr = g_Hh + ((size_t)(base + tm) + (tid >> 3)) * F_DIM + (tid & 7) * 8;
    const __half* bptr = g_W2h + ((size_t)e * F_DIM + (tid >> 4)) * D_DIM + n0 + (tid & 15) * 8;
    const uint32_t sa_o = (tid >> 3) * A_ROW_B + (tid & 7) * 16;
    const uint32_t sb_o = (tid >> 4) * B_ROW_B + (tid & 15) * 16;

    float acc[4][8][4];
#pragma unroll
    for (int mf = 0; mf < 4; mf++)
#pragma unroll
        for (int nf = 0; nf < 8; nf++)
#pragma unroll
            for (int c = 0; c < 4; c++) acc[mf][nf][c] = 0.f;

    const int KIT = F_DIM / BK;  // 32

    auto load_stage = [&](int kt) {
        const int s = kt % STAGES;
        const __half* ap = aptr + kt * BK;
        const __half* bp = bptr + (size_t)kt * BK * D_DIM;
#pragma unroll
        for (int i = 0; i < 8; i++)
            cp16(uA[s] + sa_o + i * (16 * A_ROW_B), ap + (size_t)i * 16 * F_DIM);
#pragma unroll
        for (int i = 0; i < 8; i++)
            cp16(uB[s] + sb_o + i * (8 * B_ROW_B), bp + (size_t)i * 8 * D_DIM);
        CP_COMMIT();
    };

    load_stage(0);
    load_stage(1);

    for (int kt = 0; kt < KIT; kt++) {
        if (kt + 1 < KIT) { asm volatile("cp.async.wait_group 1;"); }
        else              { asm volatile("cp.async.wait_group 0;"); }
        __syncthreads();
        if (kt + 2 < KIT) load_stage(kt + 2);
        const uint32_t ua = uA[kt % STAGES];
        const uint32_t ub = uB[kt % STAGES];
#pragma unroll
        for (int c = 0; c < 4; c++) {
            uint32_t a[4][4];
#pragma unroll
            for (int mf = 0; mf < 4; mf++) {
                int row = wm + mf * 16 + (lane & 7) + ((lane >> 3) & 1) * 8;
                LDSM_X4(a[mf], ua + row * A_ROW_B + c * 32 + (lane >> 4) * 16);
            }
            uint32_t b[8][2];
#pragma unroll
            for (int p = 0; p < 4; p++) {
                int k = c * 16 + ((lane >> 3) & 1) * 8 + (lane & 7);
                int n = wn + p * 16 + (lane >> 4) * 8;
                uint32_t r0, r1, r2, r3;
                LDSM_X4_T(r0, r1, r2, r3, ub + k * B_ROW_B + n * 2);
                b[2 * p][0] = r0; b[2 * p][1] = r1;
                b[2 * p + 1][0] = r2; b[2 * p + 1][1] = r3;
            }
#pragma unroll
            for (int mf = 0; mf < 4; mf++)
#pragma unroll
                for (int nf = 0; nf < 8; nf++)
                    mma_f16(acc[mf][nf], a[mf], b[nf]);
        }
    }

    // epilogue: bias + scatter fp32
    const int g = lane >> 2, t2 = lane & 3;
#pragma unroll
    for (int mf = 0; mf < 4; mf++) {
#pragma unroll
        for (int nf = 0; nf < 8; nf++) {
            int row0 = wm + mf * 16 + g;
            int colL = wn + nf * 8 + t2 * 2;
            float b0 = sbias[colL], b1 = sbias[colL + 1];
            int lr = tm + row0;
            if (lr < ne) {
                int tok = stoks[row0];
                float2 o = make_float2(acc[mf][nf][0] + b0, acc[mf][nf][1] + b1);
                *reinterpret_cast<float2*>(&out[(size_t)tok * D_DIM + n0 + colL]) = o;
            }
            if (lr + 8 < ne) {
                int tok = stoks[row0 + 8];
                float2 o = make_float2(acc[mf][nf][2] + b0, acc[mf][nf][3] + b1);
                *reinterpret_cast<float2*>(&out[(size_t)tok * D_DIM + n0 + colL]) = o;
            }
        }
    }
}

// ---------------- launch ----------------
extern "C" void kernel_launch(void* const* d_in, const int* in_sizes, int n_in,
                              void* d_out, int out_size)
{
    const float* X    = (const float*)d_in[0];
    const int*   disp = (const int*)d_in[1];
    const float* W1   = (const float*)d_in[2];
    const float* B1   = (const float*)d_in[3];
    const float* W2   = (const float*)d_in[4];
    const float* B2   = (const float*)d_in[5];
    float*       out  = (float*)d_out;

    cudaFuncSetAttribute(gemm1_kernel, cudaFuncAttributeMaxDynamicSharedMemorySize, DSMEM_B);
    cudaFuncSetAttribute(gemm2_kernel, cudaFuncAttributeMaxDynamicSharedMemorySize, DSMEM_B);

    __half* w1h; cudaGetSymbolAddress((void**)&w1h, g_W1h);

    dispatch_kernel<<<1, 1024>>>(disp);
    gather_x_kernel<<<T_TOKENS / 2, 256>>>(X);
    convert_w_kernel<<<WELEMS / (256 * 8), 256>>>(W1, w1h);
    // gemm1 also converts W2 -> g_W2h via its blockIdx.y==8 converter CTAs
    gemm1_kernel<<<dim3(F_DIM / BN, 9, N_EXP), NTH, DSMEM_B>>>(W2, B1);
    gemm2_kernel<<<dim3(D_DIM / BN, 8, N_EXP), NTH, DSMEM_B>>>(B2, out);
}